// round 13
// baseline (speedup 1.0000x reference)
#include <cuda_runtime.h>
#include <cuda_bf16.h>
#include <cstdint>
#include <math.h>

#define NB 8
#define NN 2048
#define DD 128
#define ROWS_TOT (NB * NN)

__device__ __nv_bfloat16 g_hhi[ROWS_TOT * DD];   // linear out (fused A/B input)
__device__ __nv_bfloat16 g_hlo[ROWS_TOT * DD];
__device__ __nv_bfloat16 g_xhi[ROWS_TOT * DD];   // fused out (next linear input)
__device__ __nv_bfloat16 g_xlo[ROWS_TOT * DD];
__device__ float g_rn[ROWS_TOT];

// ---------------------------------------------------------------------------
__device__ __forceinline__ uint32_t smem_u32(const void* p) {
    uint32_t a;
    asm("{ .reg .u64 t; cvta.to.shared.u64 t, %1; cvt.u32.u64 %0, t; }" : "=r"(a) : "l"(p));
    return a;
}
__device__ __forceinline__ void mma_bf16(float* d, const uint32_t* a, const uint32_t* b) {
    asm volatile(
        "mma.sync.aligned.m16n8k16.row.col.f32.bf16.bf16.f32 "
        "{%0,%1,%2,%3}, {%4,%5,%6,%7}, {%8,%9}, {%0,%1,%2,%3};"
        : "+f"(d[0]), "+f"(d[1]), "+f"(d[2]), "+f"(d[3])
        : "r"(a[0]), "r"(a[1]), "r"(a[2]), "r"(a[3]), "r"(b[0]), "r"(b[1]));
}
__device__ __forceinline__ void ldsm4(uint32_t* r, uint32_t addr) {
    asm volatile("ldmatrix.sync.aligned.m8n8.x4.shared.b16 {%0,%1,%2,%3}, [%4];"
                 : "=r"(r[0]), "=r"(r[1]), "=r"(r[2]), "=r"(r[3]) : "r"(addr));
}
__device__ __forceinline__ void ldsm4t(uint32_t* r, uint32_t addr) {
    asm volatile("ldmatrix.sync.aligned.m8n8.x4.trans.shared.b16 {%0,%1,%2,%3}, [%4];"
                 : "=r"(r[0]), "=r"(r[1]), "=r"(r[2]), "=r"(r[3]) : "r"(addr));
}
// hi/lo split: rn rounding identical to __float2bfloat16
__device__ __forceinline__ void split2f(float v0, float v1, uint32_t& hi, uint32_t& lo) {
    uint32_t h;
    asm("cvt.rn.bf16x2.f32 %0, %1, %2;" : "=r"(h) : "f"(v1), "f"(v0));
    const float f0 = __uint_as_float(h << 16);
    const float f1 = __uint_as_float(h & 0xffff0000u);
    const float r0 = v0 - f0;
    const float r1 = v1 - f1;
    uint32_t l;
    asm("cvt.rn.bf16x2.f32 %0, %1, %2;" : "=r"(l) : "f"(r1), "f"(r0));
    hi = h;
    lo = l;
}
#define CP_ASYNC16(dst, src) \
    asm volatile("cp.async.cg.shared.global [%0], [%1], 16;" :: "r"(dst), "l"(src))
#define CP_COMMIT() asm volatile("cp.async.commit_group;" ::: "memory")
#define CP_WAIT(n)  asm volatile("cp.async.wait_group %0;" :: "n"(n) : "memory")

#define HQS 136                          // padded bf16 row stride (272 B)

// ---------------------------------------------------------------------------
// Layer-0 linear (fp32 SIMT, proven)
// ---------------------------------------------------------------------------
#define SMEM_LIN (2 * 128 * 132 * 4)

__global__ __launch_bounds__(256, 1) void linear_norm_kernel(
    const float* __restrict__ in, const float* __restrict__ W, const float* __restrict__ bias,
    __nv_bfloat16* __restrict__ hhi, __nv_bfloat16* __restrict__ hlo, float* __restrict__ rn)
{
    extern __shared__ float sm[];
    float* sx = sm;
    float* sw = sm + 128 * 132;

    const int t = threadIdx.x;
    const int rowbase = blockIdx.x * 128;

    #pragma unroll
    for (int i = 0; i < 16; i++) {
        const int idx = i * 256 + t;
        const int r = idx >> 5, c = idx & 31;
        *(float4*)&sx[r * 132 + c * 4] = *(const float4*)&in[(size_t)(rowbase + r) * DD + c * 4];
        *(float4*)&sw[r * 132 + c * 4] = *(const float4*)&W[(size_t)r * DD + c * 4];
    }
    __syncthreads();

    const int tx = t & 15;
    const int ty = t >> 4;

    float acc[8][8];
    #pragma unroll
    for (int i = 0; i < 8; i++)
        #pragma unroll
        for (int j = 0; j < 8; j++) acc[i][j] = 0.0f;

    #pragma unroll 2
    for (int k = 0; k < DD; k++) {
        float a[8], wv[8];
        #pragma unroll
        for (int i = 0; i < 8; i++) a[i] = sx[(ty * 8 + i) * 132 + k];
        #pragma unroll
        for (int j = 0; j < 8; j++) wv[j] = sw[k * 132 + tx + 16 * j];
        #pragma unroll
        for (int i = 0; i < 8; i++)
            #pragma unroll
            for (int j = 0; j < 8; j++)
                acc[i][j] = fmaf(a[i], wv[j], acc[i][j]);
    }

    float bv[8];
    #pragma unroll
    for (int j = 0; j < 8; j++) bv[j] = bias[tx + 16 * j];

    #pragma unroll
    for (int i = 0; i < 8; i++) {
        float ss = 0.0f;
        #pragma unroll
        for (int j = 0; j < 8; j++) {
            acc[i][j] += bv[j];
            ss = fmaf(acc[i][j], acc[i][j], ss);
        }
        #pragma unroll
        for (int off = 8; off > 0; off >>= 1)
            ss += __shfl_xor_sync(0xffffffffu, ss, off, 16);
        if (tx == 0)
            rn[rowbase + ty * 8 + i] = 1.0f / fmaxf(sqrtf(ss), 1e-12f);
    }

    #pragma unroll
    for (int i = 0; i < 8; i++)
        #pragma unroll
        for (int j = 0; j < 8; j++) {
            const float v = acc[i][j];
            const __nv_bfloat16 h = __float2bfloat16(v);
            const __nv_bfloat16 l = __float2bfloat16(v - __bfloat162float(h));
            const size_t idx = (size_t)(rowbase + ty * 8 + i) * DD + tx + 16 * j;
            hhi[idx] = h;
            hlo[idx] = l;
        }
}

// ---------------------------------------------------------------------------
// Layers 1-2 linear via HMMA split (proven in R12)
// ---------------------------------------------------------------------------
#define SMEM_LH (2 * 128 * HQS * 2)

__global__ __launch_bounds__(256, 1) void linear_hmma_kernel(
    const __nv_bfloat16* __restrict__ xhi, const __nv_bfloat16* __restrict__ xlo,
    const float* __restrict__ W, const float* __restrict__ bias,
    __nv_bfloat16* __restrict__ hhi, __nv_bfloat16* __restrict__ hlo, float* __restrict__ rn)
{
    extern __shared__ char smem[];
    const uint32_t sWh = smem_u32(smem);
    const uint32_t sWl = sWh + (uint32_t)(128 * HQS * 2);

    const int t = threadIdx.x;
    const int w = t >> 5;
    const int lane = t & 31;
    const int quad = lane & 3;
    const int gr = lane >> 2;

    {
        uint32_t* wh = (uint32_t*)smem;
        uint32_t* wl = (uint32_t*)(smem + 128 * HQS * 2);
        #pragma unroll
        for (int i = 0; i < 32; i++) {
            const int pair = i * 256 + t;
            const int k = pair >> 6;
            const int n2 = (pair & 63) * 2;
            const float2 wv = *(const float2*)&W[(size_t)k * DD + n2];
            uint32_t h, l;
            split2f(wv.x, wv.y, h, l);
            wh[(k * HQS + n2) >> 1] = h;
            wl[(k * HQS + n2) >> 1] = l;
        }
    }
    __syncthreads();

    const int prow0 = blockIdx.x * 128 + w * 16 + gr;
    const int prow1 = prow0 + 8;
    const int ac = quad * 2;

    uint32_t Ahi[8][4], Alo[8][4];
    #pragma unroll
    for (int kc = 0; kc < 8; kc++) {
        Ahi[kc][0] = *(const uint32_t*)&xhi[(size_t)prow0 * DD + kc * 16 + ac];
        Ahi[kc][1] = *(const uint32_t*)&xhi[(size_t)prow1 * DD + kc * 16 + ac];
        Ahi[kc][2] = *(const uint32_t*)&xhi[(size_t)prow0 * DD + kc * 16 + 8 + ac];
        Ahi[kc][3] = *(const uint32_t*)&xhi[(size_t)prow1 * DD + kc * 16 + 8 + ac];
        Alo[kc][0] = *(const uint32_t*)&xlo[(size_t)prow0 * DD + kc * 16 + ac];
        Alo[kc][1] = *(const uint32_t*)&xlo[(size_t)prow1 * DD + kc * 16 + ac];
        Alo[kc][2] = *(const uint32_t*)&xlo[(size_t)prow0 * DD + kc * 16 + 8 + ac];
        Alo[kc][3] = *(const uint32_t*)&xlo[(size_t)prow1 * DD + kc * 16 + 8 + ac];
    }

    float C[16][4];
    #pragma unroll
    for (int i = 0; i < 16; i++)
        #pragma unroll
        for (int j = 0; j < 4; j++) C[i][j] = 0.0f;

    const uint32_t off2 = (uint32_t)((lane & 15) * (HQS * 2) + (lane >> 4) * 16);

    #pragma unroll
    for (int kc = 0; kc < 8; kc++) {
        #pragma unroll
        for (int nc = 0; nc < 8; nc++) {
            const uint32_t base = (uint32_t)(kc * 16 * (HQS * 2) + nc * 32) + off2;
            uint32_t bh[4], bl[4];
            ldsm4t(bh, sWh + base);
            mma_bf16(C[2 * nc],     Ahi[kc], bh + 0);
            mma_bf16(C[2 * nc + 1], Ahi[kc], bh + 2);
            mma_bf16(C[2 * nc],     Alo[kc], bh + 0);
            mma_bf16(C[2 * nc + 1], Alo[kc], bh + 2);
            ldsm4t(bl, sWl + base);
            mma_bf16(C[2 * nc],     Ahi[kc], bl + 0);
            mma_bf16(C[2 * nc + 1], Ahi[kc], bl + 2);
        }
    }

    float ss0 = 0.0f, ss1 = 0.0f;
    #pragma unroll
    for (int c = 0; c < 16; c++) {
        const int col = (c >> 1) * 16 + (c & 1) * 8 + ac;
        const float2 bv = *(const float2*)&bias[col];
        C[c][0] += bv.x; C[c][1] += bv.y;
        C[c][2] += bv.x; C[c][3] += bv.y;
        ss0 = fmaf(C[c][0], C[c][0], ss0);
        ss0 = fmaf(C[c][1], C[c][1], ss0);
        ss1 = fmaf(C[c][2], C[c][2], ss1);
        ss1 = fmaf(C[c][3], C[c][3], ss1);
    }
    ss0 += __shfl_xor_sync(0xffffffffu, ss0, 1);
    ss0 += __shfl_xor_sync(0xffffffffu, ss0, 2);
    ss1 += __shfl_xor_sync(0xffffffffu, ss1, 1);
    ss1 += __shfl_xor_sync(0xffffffffu, ss1, 2);
    if (quad == 0) {
        rn[prow0] = 1.0f / fmaxf(sqrtf(ss0), 1e-12f);
        rn[prow1] = 1.0f / fmaxf(sqrtf(ss1), 1e-12f);
    }

    #pragma unroll
    for (int c = 0; c < 16; c++) {
        const int col = (c >> 1) * 16 + (c & 1) * 8 + ac;
        uint32_t h0, l0, h1, l1;
        split2f(C[c][0], C[c][1], h0, l0);
        split2f(C[c][2], C[c][3], h1, l1);
        *(uint32_t*)&hhi[(size_t)prow0 * DD + col] = h0;
        *(uint32_t*)&hlo[(size_t)prow0 * DD + col] = l0;
        *(uint32_t*)&hhi[(size_t)prow1 * DD + col] = h1;
        *(uint32_t*)&hlo[(size_t)prow1 * DD + col] = l1;
    }
}

// ---------------------------------------------------------------------------
// Fused flash aggregation — cross-tile pipelined:
// GEMM1(tile i+1) interleaved with mask/split/GEMM2(tile i).
// Alo lives in smem (freed regs fund the second S bank). Triple-buffered Hq,
// double-buffered ew, one __syncthreads per iteration.
// ---------------------------------------------------------------------------
#define QT 64
#define TILE_B (QT * HQS * 2)            // 17408
#define HQ_SLOT_B (2 * TILE_B)           // 34816 (hi+lo)
#define OFF_EW (3 * HQ_SLOT_B)           // 104448
#define EWS 72
#define EW_B (128 * EWS * 4)             // 36864
#define RQ_B 256
#define STAGE_EW_B (EW_B + RQ_B)         // 37120
#define OFF_ALO (OFF_EW + 2 * STAGE_EW_B)  // 178688
#define ALO_B (128 * HQS * 2)            // 34816
#define SMEM_FUSED (OFF_ALO + ALO_B)     // 213504

#define NT (NN / QT)                     // 32 q tiles

__global__ __launch_bounds__(256, 1) void fused_mma_kernel(
    const __nv_bfloat16* __restrict__ hhi, const __nv_bfloat16* __restrict__ hlo,
    const float* __restrict__ rn, const float* __restrict__ ew,
    float* __restrict__ out, __nv_bfloat16* __restrict__ outhi,
    __nv_bfloat16* __restrict__ outlo, int mode)
{
    extern __shared__ char smem[];
    const uint32_t sbase = smem_u32(smem);

    const int t = threadIdx.x;
    const int w = t >> 5;
    const int lane = t & 31;
    const int quad = lane & 3;
    const int gr = lane >> 2;
    const int b = blockIdx.y;
    const int pbase = blockIdx.x * 128;

    const __nv_bfloat16* hhB = hhi + (size_t)b * NN * DD;
    const __nv_bfloat16* hlB = hlo + (size_t)b * NN * DD;
    const float* rnB = rn + (size_t)b * NN;
    const float* ewB = ew + (size_t)b * NN * NN;

    const int prow0 = pbase + w * 16 + gr;
    const int prow1 = prow0 + 8;
    const int ac = quad * 2;
    const int lr0 = w * 16 + gr;

    const uint32_t off1 = (uint32_t)((lane & 7) * (HQS * 2) + (lane >> 3) * 16);
    const uint32_t off2 = (uint32_t)((lane & 15) * (HQS * 2) + (lane >> 4) * 16);

    // ---- staging helpers ----
    auto stage_hq = [&](int qb, int slot) {
        const uint32_t dhi = sbase + (uint32_t)(slot * HQ_SLOT_B);
        const uint32_t dlo = dhi + TILE_B;
        #pragma unroll
        for (int i = 0; i < 4; i++) {
            const int idx = i * 256 + t;
            const int r = idx >> 4, c = idx & 15;
            const uint32_t doff = (uint32_t)(r * (HQS * 2) + c * 16);
            CP_ASYNC16(dhi + doff, (const char*)&hhB[(size_t)(qb + r) * DD + c * 8]);
            CP_ASYNC16(dlo + doff, (const char*)&hlB[(size_t)(qb + r) * DD + c * 8]);
        }
    };
    auto stage_ew = [&](int qb, int slot) {
        const uint32_t dew = sbase + OFF_EW + (uint32_t)(slot * STAGE_EW_B);
        #pragma unroll
        for (int i = 0; i < 8; i++) {
            const int idx = i * 256 + t;
            const int r = idx >> 4, c = idx & 15;
            CP_ASYNC16(dew + (uint32_t)(r * (EWS * 4) + c * 16),
                       (const char*)&ewB[(size_t)(pbase + r) * NN + qb + c * 4]);
        }
        if (t < 16)
            CP_ASYNC16(dew + (uint32_t)(EW_B + t * 16), (const char*)&rnB[qb + t * 4]);
    };
    auto stage_alo = [&]() {
        const uint32_t dst = sbase + OFF_ALO;
        #pragma unroll
        for (int i = 0; i < 8; i++) {
            const int idx = i * 256 + t;
            const int r = idx >> 4, c = idx & 15;
            CP_ASYNC16(dst + (uint32_t)(r * (HQS * 2) + c * 16),
                       (const char*)&hlB[(size_t)(pbase + r) * DD + c * 8]);
        }
    };

    // ---- prologue staging: alo + hq0 + hq1 + ew0 in one group ----
    stage_alo();
    stage_hq(0, 0);
    stage_hq(QT, 1);
    stage_ew(0, 0);
    CP_COMMIT();

    // ---- A-hi fragments (registers); A-lo comes from smem ----
    uint32_t Ahi[8][4];
    #pragma unroll
    for (int kc = 0; kc < 8; kc++) {
        Ahi[kc][0] = *(const uint32_t*)&hhB[(size_t)prow0 * DD + kc * 16 + ac];
        Ahi[kc][1] = *(const uint32_t*)&hhB[(size_t)prow1 * DD + kc * 16 + ac];
        Ahi[kc][2] = *(const uint32_t*)&hhB[(size_t)prow0 * DD + kc * 16 + 8 + ac];
        Ahi[kc][3] = *(const uint32_t*)&hhB[(size_t)prow1 * DD + kc * 16 + 8 + ac];
    }
    const float rp0 = rnB[prow0];
    const float rp1 = rnB[prow1];

    float O[16][4];
    #pragma unroll
    for (int i = 0; i < 16; i++)
        #pragma unroll
        for (int j = 0; j < 4; j++) O[i][j] = 0.0f;

    const uint32_t* sAloU = (const uint32_t*)(smem + OFF_ALO);

    // one GEMM1 chunk (kp) into S, B from hq slot (sHi/sLo)
    auto gemm1_chunk = [&](int kp, uint32_t sHi, uint32_t sLo, float (&S)[8][4]) {
        const int k0 = 2 * kp, k1 = k0 + 1;
        uint32_t a0[4], a1[4];
        a0[0] = sAloU[lr0 * 68 + k0 * 8 + quad];
        a0[1] = sAloU[(lr0 + 8) * 68 + k0 * 8 + quad];
        a0[2] = sAloU[lr0 * 68 + k0 * 8 + quad + 4];
        a0[3] = sAloU[(lr0 + 8) * 68 + k0 * 8 + quad + 4];
        a1[0] = sAloU[lr0 * 68 + k1 * 8 + quad];
        a1[1] = sAloU[(lr0 + 8) * 68 + k1 * 8 + quad];
        a1[2] = sAloU[lr0 * 68 + k1 * 8 + quad + 4];
        a1[3] = sAloU[(lr0 + 8) * 68 + k1 * 8 + quad + 4];
        #pragma unroll
        for (int nc = 0; nc < 8; nc++) {
            const uint32_t base = (uint32_t)(nc * 8 * (HQS * 2) + kp * 64) + off1;
            uint32_t bh[4], bl[4];
            ldsm4(bh, sHi + base);
            mma_bf16(S[nc], Ahi[k0], bh + 0);
            mma_bf16(S[nc], Ahi[k1], bh + 2);
            mma_bf16(S[nc], a0, bh + 0);
            mma_bf16(S[nc], a1, bh + 2);
            ldsm4(bl, sLo + base);
            mma_bf16(S[nc], Ahi[k0], bl + 0);
            mma_bf16(S[nc], Ahi[k1], bl + 2);
        }
    };

    float Sa[8][4], Sb[8][4];

    // wait prologue group, publish, compute GEMM1(tile 0) -> Sa
    CP_WAIT(0);
    __syncthreads();
    #pragma unroll
    for (int i = 0; i < 8; i++)
        #pragma unroll
        for (int j = 0; j < 4; j++) Sa[i][j] = 0.0f;
    {
        const uint32_t sHi0 = sbase;
        const uint32_t sLo0 = sbase + TILE_B;
        #pragma unroll
        for (int kp = 0; kp < 4; kp++) gemm1_chunk(kp, sHi0, sLo0, Sa);
    }

    // body: consume tile it (Scur), produce S(it+1) (Snew)
    auto body = [&](int it, float (&Scur)[8][4], float (&Snew)[8][4]) {
        CP_WAIT(0);                 // group(it-1) = {hq(it+1), ew(it)} landed
        __syncthreads();            // publish; all readers done with slots to overwrite
        if (it + 2 < NT) stage_hq((it + 2) * QT, (it + 2) % 3);
        if (it + 1 < NT) stage_ew((it + 1) * QT, (it + 1) % 2);
        CP_COMMIT();                // lands during this body's compute

        const uint32_t sHiC = sbase + (uint32_t)((it % 3) * HQ_SLOT_B);
        const uint32_t sLoC = sHiC + TILE_B;
        const uint32_t sHiN = sbase + (uint32_t)(((it + 1) % 3) * HQ_SLOT_B);
        const uint32_t sLoN = sHiN + TILE_B;
        const float* sewf = (const float*)(smem + OFF_EW + (it % 2) * STAGE_EW_B);
        const float* srqf = (const float*)(smem + OFF_EW + (it % 2) * STAGE_EW_B + EW_B);
        const bool has_next = (it + 1 < NT);

        if (has_next) {
            #pragma unroll
            for (int i = 0; i < 8; i++)
                #pragma unroll
                for (int j = 0; j < 4; j++) Snew[i][j] = 0.0f;
        }

        #pragma unroll
        for (int c = 0; c < 4; c++) {
            // ---- mask + split chunk c of tile it ----
            const int n0 = 2 * c, n1 = n0 + 1;
            uint32_t Phic[4], Ploc[4];
            {
                const int c0 = n0 * 8 + ac;
                const int c1 = n1 * 8 + ac;
                const float2 ea0 = *(const float2*)&sewf[lr0 * EWS + c0];
                const float2 ea1 = *(const float2*)&sewf[(lr0 + 8) * EWS + c0];
                const float2 ra  = *(const float2*)&srqf[c0];
                const float2 eb0 = *(const float2*)&sewf[lr0 * EWS + c1];
                const float2 eb1 = *(const float2*)&sewf[(lr0 + 8) * EWS + c1];
                const float2 rb  = *(const float2*)&srqf[c1];
                const float s00 = Scur[n0][0] * (rp0 * ra.x * ea0.x);
                const float s01 = Scur[n0][1] * (rp0 * ra.y * ea0.y);
                const float s02 = Scur[n0][2] * (rp1 * ra.x * ea1.x);
                const float s03 = Scur[n0][3] * (rp1 * ra.y * ea1.y);
                const float s10 = Scur[n1][0] * (rp0 * rb.x * eb0.x);
                const float s11 = Scur[n1][1] * (rp0 * rb.y * eb0.y);
                const float s12 = Scur[n1][2] * (rp1 * rb.x * eb1.x);
                const float s13 = Scur[n1][3] * (rp1 * rb.y * eb1.y);
                split2f(s00, s01, Phic[0], Ploc[0]);
                split2f(s02, s03, Phic[1], Ploc[1]);
                split2f(s10, s11, Phic[2], Ploc[2]);
                split2f(s12, s13, Phic[3], Ploc[3]);
            }
            // ---- GEMM2 chunk c of tile it ----
            #pragma unroll
            for (int np = 0; np < 8; np++) {
                const uint32_t base = (uint32_t)(c * 16 * (HQS * 2) + np * 32) + off2;
                uint32_t bh[4], bl[4];
                ldsm4t(bh, sHiC + base);
                mma_bf16(O[2 * np],     Phic, bh + 0);
                mma_bf16(O[2 * np + 1], Phic, bh + 2);
                mma_bf16(O[2 * np],     Ploc, bh + 0);
                mma_bf16(O[2 * np + 1], Ploc, bh + 2);
                ldsm4t(bl, sLoC + base);
                mma_bf16(O[2 * np],     Phic, bl + 0);
                mma_bf16(O[2 * np + 1], Phic, bl + 2);
            }
            // ---- GEMM1 chunk c of tile it+1 (independent; fills issue gaps) ----
            if (has_next) gemm1_chunk(c, sHiN, sLoN, Snew);
        }
    };

    for (int i2 = 0; i2 < NT / 2; i2++) {
        body(2 * i2, Sa, Sb);
        body(2 * i2 + 1, Sb, Sa);
    }

    // ---- epilogue ----
    if (mode) {
        __nv_bfloat16* ohB = outhi + (size_t)b * NN * DD;
        __nv_bfloat16* olB = outlo + (size_t)b * NN * DD;
        #pragma unroll
        for (int nc = 0; nc < 16; nc++) {
            const float v0 = fmaxf(O[nc][0], 0.0f);
            const float v1 = fmaxf(O[nc][1], 0.0f);
            const float v2 = fmaxf(O[nc][2], 0.0f);
            const float v3 = fmaxf(O[nc][3], 0.0f);
            uint32_t h0, l0, h1, l1;
            split2f(v0, v1, h0, l0);
            split2f(v2, v3, h1, l1);
            const int col = nc * 8 + ac;
            *(uint32_t*)&ohB[(size_t)prow0 * DD + col] = h0;
            *(uint32_t*)&olB[(size_t)prow0 * DD + col] = l0;
            *(uint32_t*)&ohB[(size_t)prow1 * DD + col] = h1;
            *(uint32_t*)&olB[(size_t)prow1 * DD + col] = l1;
        }
    } else {
        float* outB = out + (size_t)b * NN * DD;
        #pragma unroll
        for (int nc = 0; nc < 16; nc++) {
            *(float2*)&outB[(size_t)prow0 * DD + nc * 8 + ac] = make_float2(O[nc][0], O[nc][1]);
            *(float2*)&outB[(size_t)prow1 * DD + nc * 8 + ac] = make_float2(O[nc][2], O[nc][3]);
        }
    }
}

// ---------------------------------------------------------------------------
extern "C" void kernel_launch(void* const* d_in, const int* in_sizes, int n_in,
                              void* d_out, int out_size)
{
    const float* x  = (const float*)d_in[0];
    const float* ew = (const float*)d_in[1];
    const float* W[3]  = {(const float*)d_in[2], (const float*)d_in[4], (const float*)d_in[6]};
    const float* bb[3] = {(const float*)d_in[3], (const float*)d_in[5], (const float*)d_in[7]};
    float* out = (float*)d_out;

    float* rn;
    __nv_bfloat16 *hhi, *hlo, *xhi, *xlo;
    cudaGetSymbolAddress((void**)&rn, g_rn);
    cudaGetSymbolAddress((void**)&hhi, g_hhi);
    cudaGetSymbolAddress((void**)&hlo, g_hlo);
    cudaGetSymbolAddress((void**)&xhi, g_xhi);
    cudaGetSymbolAddress((void**)&xlo, g_xlo);

    cudaFuncSetAttribute(linear_norm_kernel,
                         cudaFuncAttributeMaxDynamicSharedMemorySize, SMEM_LIN);
    cudaFuncSetAttribute(linear_hmma_kernel,
                         cudaFuncAttributeMaxDynamicSharedMemorySize, SMEM_LH);
    cudaFuncSetAttribute(fused_mma_kernel,
                         cudaFuncAttributeMaxDynamicSharedMemorySize, SMEM_FUSED);

    const dim3 gl(ROWS_TOT / 128);
    const dim3 gf(NN / 128, NB);

    // layer 0
    linear_norm_kernel<<<gl, 256, SMEM_LIN>>>(x, W[0], bb[0], hhi, hlo, rn);
    fused_mma_kernel<<<gf, 256, SMEM_FUSED>>>(hhi, hlo, rn, ew, nullptr, xhi, xlo, 1);
    // layer 1
    linear_hmma_kernel<<<gl, 256, SMEM_LH>>>(xhi, xlo, W[1], bb[1], hhi, hlo, rn);
    fused_mma_kernel<<<gf, 256, SMEM_FUSED>>>(hhi, hlo, rn, ew, nullptr, xhi, xlo, 1);
    // layer 2
    linear_hmma_kernel<<<gl, 256, SMEM_LH>>>(xhi, xlo, W[2], bb[2], hhi, hlo, rn);
    fused_mma_kernel<<<gf, 256, SMEM_FUSED>>>(hhi, hlo, rn, ew, out, nullptr, nullptr, 0);
}

// round 14
// speedup vs baseline: 1.1589x; 1.1589x over previous
#include <cuda_runtime.h>
#include <cuda_fp16.h>
#include <cstdint>
#include <math.h>

#define NB 8
#define NN 2048
#define DD 128
#define ROWS_TOT (NB * NN)

__device__ __half g_hhi[ROWS_TOT * DD];   // linear out (fused A/B input)
__device__ __half g_hlo[ROWS_TOT * DD];
__device__ __half g_xhi[ROWS_TOT * DD];   // fused out (next linear input)
__device__ __half g_xlo[ROWS_TOT * DD];
__device__ float g_rn[ROWS_TOT];

// ---------------------------------------------------------------------------
__device__ __forceinline__ uint32_t smem_u32(const void* p) {
    uint32_t a;
    asm("{ .reg .u64 t; cvta.to.shared.u64 t, %1; cvt.u32.u64 %0, t; }" : "=r"(a) : "l"(p));
    return a;
}
__device__ __forceinline__ void mma_f16(float* d, const uint32_t* a, const uint32_t* b) {
    asm volatile(
        "mma.sync.aligned.m16n8k16.row.col.f32.f16.f16.f32 "
        "{%0,%1,%2,%3}, {%4,%5,%6,%7}, {%8,%9}, {%0,%1,%2,%3};"
        : "+f"(d[0]), "+f"(d[1]), "+f"(d[2]), "+f"(d[3])
        : "r"(a[0]), "r"(a[1]), "r"(a[2]), "r"(a[3]), "r"(b[0]), "r"(b[1]));
}
__device__ __forceinline__ void ldsm4(uint32_t* r, uint32_t addr) {
    asm volatile("ldmatrix.sync.aligned.m8n8.x4.shared.b16 {%0,%1,%2,%3}, [%4];"
                 : "=r"(r[0]), "=r"(r[1]), "=r"(r[2]), "=r"(r[3]) : "r"(addr));
}
__device__ __forceinline__ void ldsm4t(uint32_t* r, uint32_t addr) {
    asm volatile("ldmatrix.sync.aligned.m8n8.x4.trans.shared.b16 {%0,%1,%2,%3}, [%4];"
                 : "=r"(r[0]), "=r"(r[1]), "=r"(r[2]), "=r"(r[3]) : "r"(addr));
}
// fp16 hi/lo split (rn); low 16 bits = first value (even col)
__device__ __forceinline__ void split2h(float v0, float v1, uint32_t& hi, uint32_t& lo) {
    __half2 h = __floats2half2_rn(v0, v1);
    float2 f = __half22float2(h);
    __half2 l = __floats2half2_rn(v0 - f.x, v1 - f.y);
    hi = *(uint32_t*)&h;
    lo = *(uint32_t*)&l;
}
#define CP_ASYNC16(dst, src) \
    asm volatile("cp.async.cg.shared.global [%0], [%1], 16;" :: "r"(dst), "l"(src))
#define CP_COMMIT() asm volatile("cp.async.commit_group;" ::: "memory")
#define CP_WAIT(n)  asm volatile("cp.async.wait_group %0;" :: "n"(n) : "memory")

#define HQS 136                          // padded fp16 row stride (272 B)

// ---------------------------------------------------------------------------
// Layer-0 linear (fp32 SIMT, proven): x fp32 -> h split fp16 + rn
// ---------------------------------------------------------------------------
#define SMEM_LIN (2 * 128 * 132 * 4)

__global__ __launch_bounds__(256, 1) void linear_norm_kernel(
    const float* __restrict__ in, const float* __restrict__ W, const float* __restrict__ bias,
    __half* __restrict__ hhi, __half* __restrict__ hlo, float* __restrict__ rn)
{
    extern __shared__ float sm[];
    float* sx = sm;
    float* sw = sm + 128 * 132;

    const int t = threadIdx.x;
    const int rowbase = blockIdx.x * 128;

    #pragma unroll
    for (int i = 0; i < 16; i++) {
        const int idx = i * 256 + t;
        const int r = idx >> 5, c = idx & 31;
        *(float4*)&sx[r * 132 + c * 4] = *(const float4*)&in[(size_t)(rowbase + r) * DD + c * 4];
        *(float4*)&sw[r * 132 + c * 4] = *(const float4*)&W[(size_t)r * DD + c * 4];
    }
    __syncthreads();

    const int tx = t & 15;
    const int ty = t >> 4;

    float acc[8][8];
    #pragma unroll
    for (int i = 0; i < 8; i++)
        #pragma unroll
        for (int j = 0; j < 8; j++) acc[i][j] = 0.0f;

    #pragma unroll 2
    for (int k = 0; k < DD; k++) {
        float a[8], wv[8];
        #pragma unroll
        for (int i = 0; i < 8; i++) a[i] = sx[(ty * 8 + i) * 132 + k];
        #pragma unroll
        for (int j = 0; j < 8; j++) wv[j] = sw[k * 132 + tx + 16 * j];
        #pragma unroll
        for (int i = 0; i < 8; i++)
            #pragma unroll
            for (int j = 0; j < 8; j++)
                acc[i][j] = fmaf(a[i], wv[j], acc[i][j]);
    }

    float bv[8];
    #pragma unroll
    for (int j = 0; j < 8; j++) bv[j] = bias[tx + 16 * j];

    #pragma unroll
    for (int i = 0; i < 8; i++) {
        float ss = 0.0f;
        #pragma unroll
        for (int j = 0; j < 8; j++) {
            acc[i][j] += bv[j];
            ss = fmaf(acc[i][j], acc[i][j], ss);
        }
        #pragma unroll
        for (int off = 8; off > 0; off >>= 1)
            ss += __shfl_xor_sync(0xffffffffu, ss, off, 16);
        if (tx == 0)
            rn[rowbase + ty * 8 + i] = 1.0f / fmaxf(sqrtf(ss), 1e-12f);
    }

    #pragma unroll
    for (int i = 0; i < 8; i++)
        #pragma unroll
        for (int j = 0; j < 8; j++) {
            const float v = acc[i][j];
            const __half h = __float2half_rn(v);
            const __half l = __float2half_rn(v - __half2float(h));
            const size_t idx = (size_t)(rowbase + ty * 8 + i) * DD + tx + 16 * j;
            hhi[idx] = h;
            hlo[idx] = l;
        }
}

// ---------------------------------------------------------------------------
// Layers 1-2 linear via HMMA split fp16 (R12 structure, 3 products)
// ---------------------------------------------------------------------------
#define SMEM_LH (2 * 128 * HQS * 2)

__global__ __launch_bounds__(256, 1) void linear_hmma_kernel(
    const __half* __restrict__ xhi, const __half* __restrict__ xlo,
    const float* __restrict__ W, const float* __restrict__ bias,
    __half* __restrict__ hhi, __half* __restrict__ hlo, float* __restrict__ rn)
{
    extern __shared__ char smem[];
    const uint32_t sWh = smem_u32(smem);
    const uint32_t sWl = sWh + (uint32_t)(128 * HQS * 2);

    const int t = threadIdx.x;
    const int w = t >> 5;
    const int lane = t & 31;
    const int quad = lane & 3;
    const int gr = lane >> 2;

    {
        uint32_t* wh = (uint32_t*)smem;
        uint32_t* wl = (uint32_t*)(smem + 128 * HQS * 2);
        #pragma unroll
        for (int i = 0; i < 32; i++) {
            const int pair = i * 256 + t;
            const int k = pair >> 6;
            const int n2 = (pair & 63) * 2;
            const float2 wv = *(const float2*)&W[(size_t)k * DD + n2];
            uint32_t h, l;
            split2h(wv.x, wv.y, h, l);
            wh[(k * HQS + n2) >> 1] = h;
            wl[(k * HQS + n2) >> 1] = l;
        }
    }
    __syncthreads();

    const int prow0 = blockIdx.x * 128 + w * 16 + gr;
    const int prow1 = prow0 + 8;
    const int ac = quad * 2;

    uint32_t Ahi[8][4], Alo[8][4];
    #pragma unroll
    for (int kc = 0; kc < 8; kc++) {
        Ahi[kc][0] = *(const uint32_t*)&xhi[(size_t)prow0 * DD + kc * 16 + ac];
        Ahi[kc][1] = *(const uint32_t*)&xhi[(size_t)prow1 * DD + kc * 16 + ac];
        Ahi[kc][2] = *(const uint32_t*)&xhi[(size_t)prow0 * DD + kc * 16 + 8 + ac];
        Ahi[kc][3] = *(const uint32_t*)&xhi[(size_t)prow1 * DD + kc * 16 + 8 + ac];
        Alo[kc][0] = *(const uint32_t*)&xlo[(size_t)prow0 * DD + kc * 16 + ac];
        Alo[kc][1] = *(const uint32_t*)&xlo[(size_t)prow1 * DD + kc * 16 + ac];
        Alo[kc][2] = *(const uint32_t*)&xlo[(size_t)prow0 * DD + kc * 16 + 8 + ac];
        Alo[kc][3] = *(const uint32_t*)&xlo[(size_t)prow1 * DD + kc * 16 + 8 + ac];
    }

    float C[16][4];
    #pragma unroll
    for (int i = 0; i < 16; i++)
        #pragma unroll
        for (int j = 0; j < 4; j++) C[i][j] = 0.0f;

    const uint32_t off2 = (uint32_t)((lane & 15) * (HQS * 2) + (lane >> 4) * 16);

    #pragma unroll
    for (int kc = 0; kc < 8; kc++) {
        #pragma unroll
        for (int nc = 0; nc < 8; nc++) {
            const uint32_t base = (uint32_t)(kc * 16 * (HQS * 2) + nc * 32) + off2;
            uint32_t bh[4], bl[4];
            ldsm4t(bh, sWh + base);
            mma_f16(C[2 * nc],     Ahi[kc], bh + 0);
            mma_f16(C[2 * nc + 1], Ahi[kc], bh + 2);
            mma_f16(C[2 * nc],     Alo[kc], bh + 0);
            mma_f16(C[2 * nc + 1], Alo[kc], bh + 2);
            ldsm4t(bl, sWl + base);
            mma_f16(C[2 * nc],     Ahi[kc], bl + 0);
            mma_f16(C[2 * nc + 1], Ahi[kc], bl + 2);
        }
    }

    float ss0 = 0.0f, ss1 = 0.0f;
    #pragma unroll
    for (int c = 0; c < 16; c++) {
        const int col = (c >> 1) * 16 + (c & 1) * 8 + ac;
        const float2 bv = *(const float2*)&bias[col];
        C[c][0] += bv.x; C[c][1] += bv.y;
        C[c][2] += bv.x; C[c][3] += bv.y;
        ss0 = fmaf(C[c][0], C[c][0], ss0);
        ss0 = fmaf(C[c][1], C[c][1], ss0);
        ss1 = fmaf(C[c][2], C[c][2], ss1);
        ss1 = fmaf(C[c][3], C[c][3], ss1);
    }
    ss0 += __shfl_xor_sync(0xffffffffu, ss0, 1);
    ss0 += __shfl_xor_sync(0xffffffffu, ss0, 2);
    ss1 += __shfl_xor_sync(0xffffffffu, ss1, 1);
    ss1 += __shfl_xor_sync(0xffffffffu, ss1, 2);
    if (quad == 0) {
        rn[prow0] = 1.0f / fmaxf(sqrtf(ss0), 1e-12f);
        rn[prow1] = 1.0f / fmaxf(sqrtf(ss1), 1e-12f);
    }

    #pragma unroll
    for (int c = 0; c < 16; c++) {
        const int col = (c >> 1) * 16 + (c & 1) * 8 + ac;
        uint32_t h0, l0, h1, l1;
        split2h(C[c][0], C[c][1], h0, l0);
        split2h(C[c][2], C[c][3], h1, l1);
        *(uint32_t*)&hhi[(size_t)prow0 * DD + col] = h0;
        *(uint32_t*)&hlo[(size_t)prow0 * DD + col] = l0;
        *(uint32_t*)&hhi[(size_t)prow1 * DD + col] = h1;
        *(uint32_t*)&hlo[(size_t)prow1 * DD + col] = l1;
    }
}

// ---------------------------------------------------------------------------
// Fused flash aggregation (R12 skeleton, fp16). GEMM1: 3 products.
// GEMM2: 2 products (Phi*Bhi + Plo*Bhi) — B-lo product dropped (fp16
// quantization ~1.4e-4 RMS, within budget). mode 1: relu+split fp16 out.
// ---------------------------------------------------------------------------
#define QT 64
#define TILE_B (QT * HQS * 2)
#define EWS 72
#define EW_B (128 * EWS * 4)
#define RQ_B 256
#define STAGE_EW_B (EW_B + RQ_B)
#define OFF_EW (4 * TILE_B)
#define SMEM_FUSED (OFF_EW + 2 * STAGE_EW_B)

__global__ __launch_bounds__(256, 1) void fused_mma_kernel(
    const __half* __restrict__ hhi, const __half* __restrict__ hlo,
    const float* __restrict__ rn, const float* __restrict__ ew,
    float* __restrict__ out, __half* __restrict__ outhi,
    __half* __restrict__ outlo, int mode)
{
    extern __shared__ char smem[];
    const uint32_t sbase = smem_u32(smem);

    const int t = threadIdx.x;
    const int w = t >> 5;
    const int lane = t & 31;
    const int quad = lane & 3;
    const int gr = lane >> 2;
    const int b = blockIdx.y;
    const int pbase = blockIdx.x * 128;

    const __half* hhB = hhi + (size_t)b * NN * DD;
    const __half* hlB = hlo + (size_t)b * NN * DD;
    const float* rnB = rn + (size_t)b * NN;
    const float* ewB = ew + (size_t)b * NN * NN;

    const int prow0 = pbase + w * 16 + gr;
    const int prow1 = prow0 + 8;
    const int ac = quad * 2;

    uint32_t Ahi[8][4], Alo[8][4];
    #pragma unroll
    for (int kc = 0; kc < 8; kc++) {
        Ahi[kc][0] = *(const uint32_t*)&hhB[(size_t)prow0 * DD + kc * 16 + ac];
        Ahi[kc][1] = *(const uint32_t*)&hhB[(size_t)prow1 * DD + kc * 16 + ac];
        Ahi[kc][2] = *(const uint32_t*)&hhB[(size_t)prow0 * DD + kc * 16 + 8 + ac];
        Ahi[kc][3] = *(const uint32_t*)&hhB[(size_t)prow1 * DD + kc * 16 + 8 + ac];
        Alo[kc][0] = *(const uint32_t*)&hlB[(size_t)prow0 * DD + kc * 16 + ac];
        Alo[kc][1] = *(const uint32_t*)&hlB[(size_t)prow1 * DD + kc * 16 + ac];
        Alo[kc][2] = *(const uint32_t*)&hlB[(size_t)prow0 * DD + kc * 16 + 8 + ac];
        Alo[kc][3] = *(const uint32_t*)&hlB[(size_t)prow1 * DD + kc * 16 + 8 + ac];
    }
    const float rp0 = rnB[prow0];
    const float rp1 = rnB[prow1];

    float O[16][4];
    #pragma unroll
    for (int i = 0; i < 16; i++)
        #pragma unroll
        for (int j = 0; j < 4; j++) O[i][j] = 0.0f;

    const uint32_t off1 = (uint32_t)((lane & 7) * (HQS * 2) + (lane >> 3) * 16);
    const uint32_t off2 = (uint32_t)((lane & 15) * (HQS * 2) + (lane >> 4) * 16);

    auto stage = [&](int qb, int buf) {
        const uint32_t dhi = sbase + (uint32_t)(buf * 2 * TILE_B);
        const uint32_t dlo = dhi + TILE_B;
        #pragma unroll
        for (int i = 0; i < 4; i++) {
            const int idx = i * 256 + t;
            const int r = idx >> 4, c = idx & 15;
            const uint32_t doff = (uint32_t)(r * (HQS * 2) + c * 16);
            CP_ASYNC16(dhi + doff, (const char*)&hhB[(size_t)(qb + r) * DD + c * 8]);
            CP_ASYNC16(dlo + doff, (const char*)&hlB[(size_t)(qb + r) * DD + c * 8]);
        }
        const uint32_t dew = sbase + OFF_EW + (uint32_t)(buf * STAGE_EW_B);
        #pragma unroll
        for (int i = 0; i < 8; i++) {
            const int idx = i * 256 + t;
            const int r = idx >> 4, c = idx & 15;
            CP_ASYNC16(dew + (uint32_t)(r * (EWS * 4) + c * 16),
                       (const char*)&ewB[(size_t)(pbase + r) * NN + qb + c * 4]);
        }
        if (t < 16)
            CP_ASYNC16(dew + (uint32_t)(EW_B + t * 16), (const char*)&rnB[qb + t * 4]);
    };

    stage(0, 0);
    CP_COMMIT();

    for (int it = 0; it < NN / QT; it++) {
        const int qb = it * QT;
        const int cur = it & 1;
        const uint32_t sHi = sbase + (uint32_t)(cur * 2 * TILE_B);
        const uint32_t sLo = sHi + TILE_B;
        const float* sewf = (const float*)(smem + OFF_EW + cur * STAGE_EW_B);
        const float* srqf = (const float*)(smem + OFF_EW + cur * STAGE_EW_B + EW_B);

        if (qb + QT < NN) {
            stage(qb + QT, cur ^ 1);
            CP_COMMIT();
            CP_WAIT(1);
        } else {
            CP_WAIT(0);
        }
        __syncthreads();

        // ---- GEMM1: S = AhiBhi + AloBhi + AhiBlo ----
        float S[8][4];
        #pragma unroll
        for (int i = 0; i < 8; i++)
            #pragma unroll
            for (int j = 0; j < 4; j++) S[i][j] = 0.0f;

        #pragma unroll
        for (int kp = 0; kp < 4; kp++) {
            #pragma unroll
            for (int nc = 0; nc < 8; nc++) {
                const uint32_t base = (uint32_t)(nc * 8 * (HQS * 2) + kp * 64) + off1;
                uint32_t bh[4], bl[4];
                ldsm4(bh, sHi + base);
                mma_f16(S[nc], Ahi[2 * kp],     bh + 0);
                mma_f16(S[nc], Ahi[2 * kp + 1], bh + 2);
                mma_f16(S[nc], Alo[2 * kp],     bh + 0);
                mma_f16(S[nc], Alo[2 * kp + 1], bh + 2);
                ldsm4(bl, sLo + base);
                mma_f16(S[nc], Ahi[2 * kp],     bl + 0);
                mma_f16(S[nc], Ahi[2 * kp + 1], bl + 2);
            }
        }

        // ---- fused mask + split + GEMM2 (2 products), per k-chunk ----
        const int lr0 = w * 16 + gr;
        #pragma unroll
        for (int kc = 0; kc < 4; kc++) {
            const int n0 = 2 * kc, n1 = n0 + 1;
            uint32_t Phic[4], Ploc[4];
            {
                const int c0 = n0 * 8 + ac;
                const int c1 = n1 * 8 + ac;
                const float2 ea0 = *(const float2*)&sewf[lr0 * EWS + c0];
                const float2 ea1 = *(const float2*)&sewf[(lr0 + 8) * EWS + c0];
                const float2 ra  = *(const float2*)&srqf[c0];
                const float2 eb0 = *(const float2*)&sewf[lr0 * EWS + c1];
                const float2 eb1 = *(const float2*)&sewf[(lr0 + 8) * EWS + c1];
                const float2 rb  = *(const float2*)&srqf[c1];
                const float s00 = S[n0][0] * (rp0 * ra.x * ea0.x);
                const float s01 = S[n0][1] * (rp0 * ra.y * ea0.y);
                const float s02 = S[n0][2] * (rp1 * ra.x * ea1.x);
                const float s03 = S[n0][3] * (rp1 * ra.y * ea1.y);
                const float s10 = S[n1][0] * (rp0 * rb.x * eb0.x);
                const float s11 = S[n1][1] * (rp0 * rb.y * eb0.y);
                const float s12 = S[n1][2] * (rp1 * rb.x * eb1.x);
                const float s13 = S[n1][3] * (rp1 * rb.y * eb1.y);
                split2h(s00, s01, Phic[0], Ploc[0]);
                split2h(s02, s03, Phic[1], Ploc[1]);
                split2h(s10, s11, Phic[2], Ploc[2]);
                split2h(s12, s13, Phic[3], Ploc[3]);
            }
            #pragma unroll
            for (int np = 0; np < 8; np++) {
                const uint32_t base = (uint32_t)(kc * 16 * (HQS * 2) + np * 32) + off2;
                uint32_t bh[4];
                ldsm4t(bh, sHi + base);
                mma_f16(O[2 * np],     Phic, bh + 0);
                mma_f16(O[2 * np + 1], Phic, bh + 2);
                mma_f16(O[2 * np],     Ploc, bh + 0);
                mma_f16(O[2 * np + 1], Ploc, bh + 2);
            }
        }
        __syncthreads();
    }

    // ---- epilogue ----
    if (mode) {
        __half* ohB = outhi + (size_t)b * NN * DD;
        __half* olB = outlo + (size_t)b * NN * DD;
        #pragma unroll
        for (int nc = 0; nc < 16; nc++) {
            const float v0 = fmaxf(O[nc][0], 0.0f);
            const float v1 = fmaxf(O[nc][1], 0.0f);
            const float v2 = fmaxf(O[nc][2], 0.0f);
            const float v3 = fmaxf(O[nc][3], 0.0f);
            uint32_t h0, l0, h1, l1;
            split2h(v0, v1, h0, l0);
            split2h(v2, v3, h1, l1);
            const int col = nc * 8 + ac;
            *(uint32_t*)&ohB[(size_t)prow0 * DD + col] = h0;
            *(uint32_t*)&olB[(size_t)prow0 * DD + col] = l0;
            *(uint32_t*)&ohB[(size_t)prow1 * DD + col] = h1;
            *(uint32_t*)&olB[(size_t)prow1 * DD + col] = l1;
        }
    } else {
        float* outB = out + (size_t)b * NN * DD;
        #pragma unroll
        for (int nc = 0; nc < 16; nc++) {
            *(float2*)&outB[(size_t)prow0 * DD + nc * 8 + ac] = make_float2(O[nc][0], O[nc][1]);
            *(float2*)&outB[(size_t)prow1 * DD + nc * 8 + ac] = make_float2(O[nc][2], O[nc][3]);
        }
    }
}

// ---------------------------------------------------------------------------
extern "C" void kernel_launch(void* const* d_in, const int* in_sizes, int n_in,
                              void* d_out, int out_size)
{
    const float* x  = (const float*)d_in[0];
    const float* ew = (const float*)d_in[1];
    const float* W[3]  = {(const float*)d_in[2], (const float*)d_in[4], (const float*)d_in[6]};
    const float* bb[3] = {(const float*)d_in[3], (const float*)d_in[5], (const float*)d_in[7]};
    float* out = (float*)d_out;

    float* rn;
    __half *hhi, *hlo, *xhi, *xlo;
    cudaGetSymbolAddress((void**)&rn, g_rn);
    cudaGetSymbolAddress((void**)&hhi, g_hhi);
    cudaGetSymbolAddress((void**)&hlo, g_hlo);
    cudaGetSymbolAddress((void**)&xhi, g_xhi);
    cudaGetSymbolAddress((void**)&xlo, g_xlo);

    cudaFuncSetAttribute(linear_norm_kernel,
                         cudaFuncAttributeMaxDynamicSharedMemorySize, SMEM_LIN);
    cudaFuncSetAttribute(linear_hmma_kernel,
                         cudaFuncAttributeMaxDynamicSharedMemorySize, SMEM_LH);
    cudaFuncSetAttribute(fused_mma_kernel,
                         cudaFuncAttributeMaxDynamicSharedMemorySize, SMEM_FUSED);

    const dim3 gl(ROWS_TOT / 128);
    const dim3 gf(NN / 128, NB);

    // layer 0
    linear_norm_kernel<<<gl, 256, SMEM_LIN>>>(x, W[0], bb[0], hhi, hlo, rn);
    fused_mma_kernel<<<gf, 256, SMEM_FUSED>>>(hhi, hlo, rn, ew, nullptr, xhi, xlo, 1);
    // layer 1
    linear_hmma_kernel<<<gl, 256, SMEM_LH>>>(xhi, xlo, W[1], bb[1], hhi, hlo, rn);
    fused_mma_kernel<<<gf, 256, SMEM_FUSED>>>(hhi, hlo, rn, ew, nullptr, xhi, xlo, 1);
    // layer 2
    linear_hmma_kernel<<<gl, 256, SMEM_LH>>>(xhi, xlo, W[2], bb[2], hhi, hlo, rn);
    fused_mma_kernel<<<gf, 256, SMEM_FUSED>>>(hhi, hlo, rn, ew, out, nullptr, nullptr, 0);
}